// round 15
// baseline (speedup 1.0000x reference)
#include <cuda_runtime.h>
#include <cuda_fp16.h>
#include <math.h>
#include <stdint.h>

#define T_TOK 512
#define D_DIM 1024
#define E_EXP 64
#define F_INT 512
#define TOPK  4

#define ROWB 144   // 64 fp16 = 128B data + 16B pad: conflict-free ldmatrix, swizzle-free
#define NTOK 64    // token tile; act-gating skips unused 16-token columns

// ---------------- persistent device scratch ----------------------------------
__device__ float g_logits[T_TOK * E_EXP];
__device__ float g_topk_w[T_TOK * TOPK];
__device__ int   g_exp_cnt[E_EXP];
__device__ int   g_exp_tok[E_EXP * T_TOK];                 // entry = token*4 + slot
__device__ __half g_H[T_TOK * TOPK * F_INT];               // 2 MB (fp16)
__device__ __half g_Y[T_TOK * TOPK * D_DIM];               // 4 MB (fp16)

// ---------------- helpers -----------------------------------------------------
__device__ __forceinline__ uint32_t smem_u32(const void* p) {
    uint32_t a;
    asm("{ .reg .u64 t; cvta.to.shared.u64 t, %1; cvt.u32.u64 %0, t; }" : "=r"(a) : "l"(p));
    return a;
}
__device__ __forceinline__ void ldm4(uint32_t* r, uint32_t a) {
    asm volatile("ldmatrix.sync.aligned.m8n8.x4.shared.b16 {%0,%1,%2,%3}, [%4];"
        : "=r"(r[0]), "=r"(r[1]), "=r"(r[2]), "=r"(r[3]) : "r"(a));
}
__device__ __forceinline__ void mma16816(float* d, const uint32_t* a, const uint32_t* b) {
    asm volatile("mma.sync.aligned.m16n8k16.row.col.f32.f16.f16.f32 "
        "{%0,%1,%2,%3}, {%4,%5,%6,%7}, {%8,%9}, {%0,%1,%2,%3};"
        : "+f"(d[0]), "+f"(d[1]), "+f"(d[2]), "+f"(d[3])
        : "r"(a[0]), "r"(a[1]), "r"(a[2]), "r"(a[3]), "r"(b[0]), "r"(b[1]));
}
__device__ __forceinline__ uint32_t pack_h2(float a, float b) {
    __half2 h = __floats2half2_rn(a, b);
    return *reinterpret_cast<uint32_t*>(&h);
}
// split 8 contiguous fp32 into 16B fp16-hi + 16B fp16-lo
__device__ __forceinline__ void cvt_split8(const float4* v, uint4& h, uint4& l) {
    const float* f = (const float*)v;
    uint32_t hp[4], lp[4];
#pragma unroll
    for (int i = 0; i < 4; i++) {
        float a = f[2 * i], b = f[2 * i + 1];
        __half ha = __float2half_rn(a), hb = __float2half_rn(b);
        hp[i] = (uint32_t)__half_as_ushort(ha) | ((uint32_t)__half_as_ushort(hb) << 16);
        lp[i] = pack_h2(a - __half2float(ha), b - __half2float(hb));
    }
    h = make_uint4(hp[0], hp[1], hp[2], hp[3]);
    l = make_uint4(lp[0], lp[1], lp[2], lp[3]);
}
__device__ __forceinline__ void cvt_h8(const float4* v, uint4& h) {
    const float* f = (const float*)v;
    h = make_uint4(pack_h2(f[0], f[1]), pack_h2(f[2], f[3]),
                   pack_h2(f[4], f[5]), pack_h2(f[6], f[7]));
}
__device__ __forceinline__ void sts8(const float4* v, char* hi, char* lo, int off) {
    uint4 h, l;
    cvt_split8(v, h, l);
    *(uint4*)(hi + off) = h;
    *(uint4*)(lo + off) = l;
}
__device__ __forceinline__ void ldg8(float4* v, const float* rowbase, int k0, int q) {
    v[0] = *(const float4*)(rowbase + k0 + (q << 3));
    v[1] = *(const float4*)(rowbase + k0 + (q << 3) + 4);
}

// ---------------- 1: router logits (block 0 also zeroes expert counts) --------
__global__ __launch_bounds__(256) void logits_kernel(
    const float* __restrict__ x, const float* __restrict__ gw)
{
    const int tblk = blockIdx.x * 8;
    const int tid  = threadIdx.x;
    if (blockIdx.x == 0 && tid < E_EXP) g_exp_cnt[tid] = 0;
    __shared__ __align__(16) float As[32][12];
    __shared__ __align__(16) float Bs[32][68];
    const int ttok = tid >> 5;          // 0..7
    const int te   = (tid & 31) << 1;   // 0..62
    float acc0 = 0.f, acc1 = 0.f;

    for (int k0 = 0; k0 < D_DIM; k0 += 32) {
        if (tid < 64) {
            int tok = tid >> 3, kk4 = tid & 7;
            float4 v = *(const float4*)(x + (size_t)(tblk + tok) * D_DIM + k0 + (kk4 << 2));
            As[(kk4 << 2) + 0][tok] = v.x;
            As[(kk4 << 2) + 1][tok] = v.y;
            As[(kk4 << 2) + 2][tok] = v.z;
            As[(kk4 << 2) + 3][tok] = v.w;
        }
#pragma unroll
        for (int j = 0; j < 2; j++) {
            int idx = tid + (j << 8);
            int r = idx >> 3, kk4 = idx & 7;
            float4 v = *(const float4*)(gw + (size_t)r * D_DIM + k0 + (kk4 << 2));
            Bs[(kk4 << 2) + 0][r] = v.x;
            Bs[(kk4 << 2) + 1][r] = v.y;
            Bs[(kk4 << 2) + 2][r] = v.z;
            Bs[(kk4 << 2) + 3][r] = v.w;
        }
        __syncthreads();
#pragma unroll
        for (int kk = 0; kk < 32; kk++) {
            float a = As[kk][ttok];
            acc0 += a * Bs[kk][te];
            acc1 += a * Bs[kk][te + 1];
        }
        __syncthreads();
    }
    g_logits[(size_t)(tblk + ttok) * E_EXP + te]     = acc0;
    g_logits[(size_t)(tblk + ttok) * E_EXP + te + 1] = acc1;
}

// ---------------- 2: per-token top-4 + renorm + expert lists ------------------
__global__ void topk_kernel()
{
    const int t = blockIdx.x;
    const int lane = threadIdx.x;
    float c0 = g_logits[t * E_EXP + lane];
    float c1 = g_logits[t * E_EXP + lane + 32];
    float selv[4]; int seli[4];
#pragma unroll
    for (int s = 0; s < 4; s++) {
        float bv; int bi;
        if (c0 >= c1) { bv = c0; bi = lane; } else { bv = c1; bi = lane + 32; }
#pragma unroll
        for (int off = 16; off > 0; off >>= 1) {
            float ov = __shfl_xor_sync(0xffffffffu, bv, off);
            int   oi = __shfl_xor_sync(0xffffffffu, bi, off);
            if (ov > bv || (ov == bv && oi < bi)) { bv = ov; bi = oi; }
        }
        selv[s] = bv; seli[s] = bi;
        if (bi == lane)      c0 = -3.0e38f;
        if (bi == lane + 32) c1 = -3.0e38f;
    }
    if (lane == 0) {
        float m = selv[0];
        float ew[4]; float sum = 0.f;
#pragma unroll
        for (int s = 0; s < 4; s++) { ew[s] = expf(selv[s] - m); sum += ew[s]; }
        float inv = 1.f / sum;
#pragma unroll
        for (int s = 0; s < 4; s++) {
            g_topk_w[t * 4 + s] = ew[s] * inv;
            int ee = seli[s];
            int pos = atomicAdd(&g_exp_cnt[ee], 1);
            g_exp_tok[ee * T_TOK + pos] = t * 4 + s;
        }
    }
}

// ---------------- 3: Stage A — HMMA gate/up GEMM + in-register SiLU -----------
// CTA = (fchunk 0..15, expert), 256 threads, 4 CTAs/SM.
// Tile: 32 f x (act*16) tok. Warp grid 2(M) x 4(N); warp tile [16 x 16].
#define OFF_AGH 0
#define OFF_AGL 4608
#define OFF_AUH 9216
#define OFF_AUL 13824
#define OFF_BH  18432
#define BUF_A   27648

__device__ __forceinline__ void kstepA(uint32_t cb, int s, int a_off, int b_off,
                                       float* accg, float* accu)
{
    const int so = s << 5;
    uint32_t agh[4], agl[4], auh[4], aul[4], bh[4];
    ldm4(agh, cb + OFF_AGH + a_off + so);
    ldm4(agl, cb + OFF_AGL + a_off + so);
    ldm4(auh, cb + OFF_AUH + a_off + so);
    ldm4(aul, cb + OFF_AUL + a_off + so);
    ldm4(bh,  cb + OFF_BH  + b_off + so);
#pragma unroll
    for (int nt = 0; nt < 2; nt++) {
        mma16816(accg + nt * 4, agh, bh + nt * 2);
        mma16816(accg + nt * 4, agl, bh + nt * 2);
        mma16816(accu + nt * 4, auh, bh + nt * 2);
        mma16816(accu + nt * 4, aul, bh + nt * 2);
    }
}

__global__ __launch_bounds__(256, 4) void stageA_mma(
    const float* __restrict__ x,
    const float* __restrict__ wg,
    const float* __restrict__ wu)
{
    const int e = blockIdx.y, fc = blockIdx.x;
    const int cnt = g_exp_cnt[e];
    if (cnt == 0) return;
    extern __shared__ __align__(16) char dsm[];
    __shared__ int ent[NTOK];
    const int tid = threadIdx.x, wid = tid >> 5, lane = tid & 31;
    const int wm = wid >> 2, wn = wid & 3;   // 2(M) x 4(N)
    const uint32_t smA = smem_u32(dsm);

    const float* wgB = wg + ((size_t)e * F_INT + fc * 32) * D_DIM;
    const float* wuB = wu + ((size_t)e * F_INT + fc * 32) * D_DIM;

    const int a_off = ((wm << 4) + (lane & 15)) * ROWB + ((lane >> 4) << 4);
    const int b_off = ((wn << 4) + ((lane >> 4) << 3) + (lane & 7)) * ROWB
                    + (((lane >> 3) & 1) << 4);
    const int r8 = tid >> 3, q8 = tid & 7;          // weight loader row/seg (32 rows)
    const int soff = r8 * ROWB + (q8 << 4);
    const float* wgRow = wgB + (size_t)r8 * D_DIM;
    const float* wuRow = wuB + (size_t)r8 * D_DIM;
    // x loader: two slots (rows r8 and r8+32)
    const int xr1 = r8 + 32;
    const int soff1 = xr1 * ROWB + (q8 << 4);

    for (int base = 0; base < cnt; base += NTOK) {
        __syncthreads();
        if (tid < NTOK) ent[tid] = (base + tid < cnt) ? g_exp_tok[e * T_TOK + base + tid] : -1;
        __syncthreads();

        const int rem = cnt - base;
        const int act = min(4, ((rem < NTOK ? rem : NTOK) + 15) >> 4);
        const bool mmaOn  = (wn < act);
        const bool stg0 = (r8  < (act << 4));
        const bool stg1 = (xr1 < (act << 4));

        const int en0 = ent[r8];
        const int en1 = ent[xr1];
        const float* xRow0 = (en0 >= 0) ? (x + (size_t)(en0 >> 2) * D_DIM) : 0;
        const float* xRow1 = (en1 >= 0) ? (x + (size_t)(en1 >> 2) * D_DIM) : 0;

        {   // prologue: chunk 0 -> buffer 0
            char* B0 = dsm;
            float4 vg[2], vu[2], vx0[2], vx1[2];
            ldg8(vg, wgRow, 0, q8);
            ldg8(vu, wuRow, 0, q8);
            if (stg0) {
                if (xRow0) ldg8(vx0, xRow0, 0, q8);
                else { vx0[0] = make_float4(0.f,0.f,0.f,0.f); vx0[1] = vx0[0]; }
            }
            if (stg1) {
                if (xRow1) ldg8(vx1, xRow1, 0, q8);
                else { vx1[0] = make_float4(0.f,0.f,0.f,0.f); vx1[1] = vx1[0]; }
            }
            sts8(vg, B0 + OFF_AGH, B0 + OFF_AGL, soff);
            sts8(vu, B0 + OFF_AUH, B0 + OFF_AUL, soff);
            if (stg0) { uint4 h; cvt_h8(vx0, h); *(uint4*)(B0 + OFF_BH + soff)  = h; }
            if (stg1) { uint4 h; cvt_h8(vx1, h); *(uint4*)(B0 + OFF_BH + soff1) = h; }
        }
        float accg[8], accu[8];
#pragma unroll
        for (int i = 0; i < 8; i++) { accg[i] = 0.f; accu[i] = 0.f; }

        for (int kt = 0; kt < 16; kt++) {
            __syncthreads();
            const uint32_t cb = smA + (uint32_t)((kt & 1) * BUF_A);
            char* NB = dsm + ((kt + 1) & 1) * BUF_A;
            const bool more = (kt < 15);
            const int k0n = (kt + 1) << 6;

            float4 vg[2], vu[2], vx0[2], vx1[2];
            if (more) {
                ldg8(vg, wgRow, k0n, q8);
                ldg8(vu, wuRow, k0n, q8);
                if (stg0) {
                    if (xRow0) ldg8(vx0, xRow0, k0n, q8);
                    else { vx0[0] = make_float4(0.f,0.f,0.f,0.f); vx0[1] = vx0[0]; }
                }
                if (stg1) {
                    if (xRow1) ldg8(vx1, xRow1, k0n, q8);
                    else { vx1[0] = make_float4(0.f,0.f,0.f,0.f); vx1[1] = vx1[0]; }
                }
            }
            if (mmaOn) { kstepA(cb, 0, a_off, b_off, accg, accu);
                         kstepA(cb, 1, a_off, b_off, accg, accu); }
            if (more) sts8(vg, NB + OFF_AGH, NB + OFF_AGL, soff);
            if (mmaOn) kstepA(cb, 2, a_off, b_off, accg, accu);
            if (more) sts8(vu, NB + OFF_AUH, NB + OFF_AUL, soff);
            if (mmaOn) kstepA(cb, 3, a_off, b_off, accg, accu);
            if (more) {
                if (stg0) { uint4 h; cvt_h8(vx0, h); *(uint4*)(NB + OFF_BH + soff)  = h; }
                if (stg1) { uint4 h; cvt_h8(vx1, h); *(uint4*)(NB + OFF_BH + soff1) = h; }
            }
        }

        // epilogue: silu(g)*u in regs -> smem transpose -> coalesced fp16 writeout
        __syncthreads();
        float* sm_h = (float*)dsm;            // [64 tok][36]
        if (mmaOn) {
            const int fr = (wm << 4) + (lane >> 2);
            const int tc = (wn << 4) + ((lane & 3) << 1);
#pragma unroll
            for (int nt = 0; nt < 2; nt++) {
#pragma unroll
                for (int q = 0; q < 4; q++) {
                    int f = fr + ((q >> 1) << 3);
                    int t = tc + (nt << 3) + (q & 1);
                    float g = accg[nt * 4 + q], u = accu[nt * 4 + q];
                    float h = g / (1.f + __expf(-g)) * u;
                    sm_h[t * 36 + f] = h;
                }
            }
        }
        __syncthreads();
        {   // thread: token tt = tid>>2, 8-f segment sg = tid&3
            const int tt = tid >> 2, sg = tid & 3;
            const int ec = ent[tt];
            if (ec >= 0) {
                const float4* src = (const float4*)(sm_h + tt * 36 + (sg << 3));
                float4 v[2] = { src[0], src[1] };
                uint4 h; cvt_h8(v, h);
                *(uint4*)(g_H + (size_t)ec * F_INT + fc * 32 + (sg << 3)) = h;
            }
        }
    }
}

// ---------------- 4: Stage B — HMMA down GEMM --------------------------------
// CTA = (dchunk 0..31, expert), 256 threads, 4 CTAs/SM. Tile: 32 d x (act*16) tok.
#define OFF_ADH 0
#define OFF_ADL 4608
#define OFF_BBH 9216
#define BUF_B   18432

__device__ __forceinline__ void kstepB(uint32_t cb, int s, int a_off, int b_off, float* acc)
{
    const int so = s << 5;
    uint32_t adh[4], adl[4], bh[4];
    ldm4(adh, cb + OFF_ADH + a_off + so);
    ldm4(adl, cb + OFF_ADL + a_off + so);
    ldm4(bh,  cb + OFF_BBH + b_off + so);
#pragma unroll
    for (int nt = 0; nt < 2; nt++) {
        mma16816(acc + nt * 4, adh, bh + nt * 2);
        mma16816(acc + nt * 4, adl, bh + nt * 2);
    }
}

__global__ __launch_bounds__(256, 4) void stageB_mma(const float* __restrict__ wd)
{
    const int e = blockIdx.y, dc = blockIdx.x;
    const int cnt = g_exp_cnt[e];
    if (cnt == 0) return;
    extern __shared__ __align__(16) char dsm[];
    __shared__ int ent[NTOK];
    const int tid = threadIdx.x, wid = tid >> 5, lane = tid & 31;
    const int wm = wid >> 2, wn = wid & 3;
    const uint32_t smA = smem_u32(dsm);

    const float* wdB = wd + ((size_t)e * D_DIM + dc * 32) * F_INT;
    const int a_off = ((wm << 4) + (lane & 15)) * ROWB + ((lane >> 4) << 4);
    const int b_off = ((wn << 4) + ((lane >> 4) << 3) + (lane & 7)) * ROWB
                    + (((lane >> 3) & 1) << 4);
    const int r8 = tid >> 3, q8 = tid & 7;
    const int soff = r8 * ROWB + (q8 << 4);
    const float* wdRow = wdB + (size_t)r8 * F_INT;
    const int hr1 = r8 + 32;
    const int soff1 = hr1 * ROWB + (q8 << 4);

    for (int base = 0; base < cnt; base += NTOK) {
        __syncthreads();
        if (tid < NTOK) ent[tid] = (base + tid < cnt) ? g_exp_tok[e * T_TOK + base + tid] : -1;
        __syncthreads();

        const int rem = cnt - base;
        const int act = min(4, ((rem < NTOK ? rem : NTOK) + 15) >> 4);
        const bool mmaOn = (wn < act);
        const bool stg0 = (r8  < (act << 4));
        const bool stg1 = (hr1 < (act << 4));

        const int en0 = ent[r8];
        const int en1 = ent[hr1];
        const __half* hRow0 = (en0 >= 0) ? (g_H + (size_t)en0 * F_INT) : 0;
        const __half* hRow1 = (en1 >= 0) ? (g_H + (size_t)en1 * F_INT) : 0;

        {   // prologue: chunk 0 -> buffer 0
            char* B0 = dsm;
            float4 v[2];
            uint4 v0 = make_uint4(0,0,0,0), v1 = make_uint4(0,0,0,0);
            ldg8(v, wdRow, 0, q8);
            if (stg0 && hRow0) v0 = *(const uint4*)(hRow0 + (q8 << 3));
            if (stg1 && hRow1) v1 = *(const uint4*)(hRow1 + (q8 << 3));
            sts8(v, B0 + OFF_ADH, B0 + OFF_ADL, soff);
            if (stg0) *(uint4*)(B0 + OFF_BBH + soff)  = v0;
            if (stg1) *(uint4*)(B0 + OFF_BBH + soff1) = v1;
        }
        float acc[8];
#pragma unroll
        for (int i = 0; i < 8; i++) acc[i] = 0.f;

        for (int kt = 0; kt < 8; kt++) {
            __syncthreads();
            const uint32_t cb = smA + (uint32_t)((kt & 1) * BUF_B);
            char* NB = dsm + ((kt + 1) & 1) * BUF_B;
            const bool more = (kt < 7);
            const int k0n = (kt + 1) << 6;

            float4 v[2];
            uint4 v0 = make_uint4(0,0,0,0), v1 = make_uint4(0,0,0,0);
            if (more) {
                ldg8(v, wdRow, k0n, q8);
                if (stg0 && hRow0) v0 = *(const uint4*)(hRow0 + k0n + (q8 << 3));
                if (stg1 && hRow1) v1 = *(const uint4*)(hRow1 + k0n + (q8 << 3));
            }
            if (mmaOn) { kstepB(cb, 0, a_off, b_off, acc);
                         kstepB(cb, 1, a_off, b_off, acc); }
            if (more) sts8(v, NB + OFF_ADH, NB + OFF_ADL, soff);
            if (mmaOn) { kstepB(cb, 2, a_off, b_off, acc);
                         kstepB(cb, 3, a_off, b_off, acc); }
            if (more) {
                if (stg0) *(uint4*)(NB + OFF_BBH + soff)  = v0;
                if (stg1) *(uint4*)(NB + OFF_BBH + soff1) = v1;
            }
        }

        // epilogue: smem transpose -> coalesced fp16 writeout
        __syncthreads();
        float* sm_y = (float*)dsm;            // [64 tok][36]
        if (mmaOn) {
            const int dr = (wm << 4) + (lane >> 2);
            const int tc = (wn << 4) + ((lane & 3) << 1);
#pragma unroll
            for (int nt = 0; nt < 2; nt++) {
#pragma unroll
                for (int q = 0; q < 4; q++) {
                    int d = dr + ((q >> 1) << 3);
                    int t = tc + (nt << 3) + (q & 1);
                    sm_y[t * 36 + d] = acc[nt * 4 + q];
                }
            }
        }
        __syncthreads();
        {
            const int tt = tid >> 2, sg = tid & 3;
            const int ec = ent[tt];
            if (ec >= 0) {
                const float4* src = (const float4*)(sm_y + tt * 36 + (sg << 3));
                float4 v[2] = { src[0], src[1] };
                uint4 h; cvt_h8(v, h);
                *(uint4*)(g_Y + (size_t)ec * D_DIM + dc * 32 + (sg << 3)) = h;
            }
        }
    }
}

// ---------------- 5: weighted combine (fp16 Y -> fp32 out) -------------------
__global__ void combine_kernel(float* __restrict__ out)
{
    const int t = blockIdx.x;
    const int d = threadIdx.x << 2;
    const float w0 = g_topk_w[t * 4 + 0];
    const float w1 = g_topk_w[t * 4 + 1];
    const float w2 = g_topk_w[t * 4 + 2];
    const float w3 = g_topk_w[t * 4 + 3];
    const __half* yb = g_Y + (size_t)t * 4 * D_DIM;
    float o[4] = {0.f, 0.f, 0.f, 0.f};
    const float w[4] = {w0, w1, w2, w3};
#pragma unroll
    for (int s = 0; s < 4; s++) {
        uint2 p = *(const uint2*)(yb + s * D_DIM + d);
        __half2 h01 = *reinterpret_cast<__half2*>(&p.x);
        __half2 h23 = *reinterpret_cast<__half2*>(&p.y);
        float2 f01 = __half22float2(h01);
        float2 f23 = __half22float2(h23);
        o[0] += w[s] * f01.x; o[1] += w[s] * f01.y;
        o[2] += w[s] * f23.x; o[3] += w[s] * f23.y;
    }
    *(float4*)(out + (size_t)t * D_DIM + d) = make_float4(o[0], o[1], o[2], o[3]);
}

// ---------------- launch ------------------------------------------------------
extern "C" void kernel_launch(void* const* d_in, const int* in_sizes, int n_in,
                              void* d_out, int out_size)
{
    (void)in_sizes; (void)n_in; (void)out_size;
    const float* x  = (const float*)d_in[0];
    const float* gw = (const float*)d_in[1];
    const float* wg = (const float*)d_in[2];
    const float* wu = (const float*)d_in[3];
    const float* wd = (const float*)d_in[4];
    float* out = (float*)d_out;

    const int smemA = 2 * BUF_A;   // 55296 -> 4 CTAs/SM
    const int smemB = 2 * BUF_B;   // 36864 -> 4 CTAs/SM
    cudaFuncSetAttribute(stageA_mma, cudaFuncAttributeMaxDynamicSharedMemorySize, smemA);
    cudaFuncSetAttribute(stageB_mma, cudaFuncAttributeMaxDynamicSharedMemorySize, smemB);

    logits_kernel <<<64, 256>>>(x, gw);
    topk_kernel   <<<T_TOK, 32>>>();
    stageA_mma    <<<dim3(16, E_EXP), 256, smemA>>>(x, wg, wu);
    stageB_mma    <<<dim3(32, E_EXP), 256, smemB>>>(wd);
    combine_kernel<<<T_TOK, 256>>>(out);
}